// round 1
// baseline (speedup 1.0000x reference)
#include <cuda_runtime.h>

#define NB 16            // batch
#define NS 65            // segments per batch
#define NR 1040          // NB*NS rows
#define NW 256           // candidate positions per row
#define ND 128           // feature dim
#define T_PAD 2176       // padded time length of x
#define LSEQ 2048        // MAX_LEN_SEQ
#define MIN_SEG 32

__device__ int g_cnt[NR];
__device__ int g_offset[NR];
__device__ int g_rowstart[NR + 1];
__device__ int g_L[1];

// ---------------------------------------------------------------------------
// Kernel 1: per segment-row, compute cumulative segment offset + masked count.
// One warp per row. Mask is a prefix in w (both conditions monotone), so only
// the count is needed.
// ---------------------------------------------------------------------------
__global__ void count_kernel(const float* __restrict__ scales,
                             const int* __restrict__ len_seq,
                             const int* __restrict__ len_seg_raw) {
    int warp = (blockIdx.x * blockDim.x + threadIdx.x) >> 5;
    int lane = threadIdx.x & 31;
    if (warp >= NR) return;
    int r = warp;
    int b = r / NS;
    int s = r - b * NS;

    // exclusive per-batch cumsum of len_seg = len_seg_raw + MIN_SEG
    int part = 0;
    for (int j = lane; j < s; j += 32) part += len_seg_raw[b * NS + j];
    #pragma unroll
    for (int o = 16; o > 0; o >>= 1) part += __shfl_xor_sync(0xffffffffu, part, o);
    int offset = part + MIN_SEG * s;

    float sc      = scales[r] + 0.5f;
    float lseg_m1 = (float)(len_seg_raw[r] + MIN_SEG) - 1.0f;
    float lseq_m1 = (float)len_seq[b] - 1.0f;
    float foff    = (float)offset;   // <= 8320, exact in fp32

    int cnt = 0;
    for (int w = lane; w < NW; w += 32) {
        float fs = __fdiv_rn((float)w, sc);   // IEEE div, matches jnp exactly
        float fl = floorf(fs);
        bool m = (fl < lseg_m1) && (fl + foff < lseq_m1);
        cnt += m ? 1 : 0;
    }
    #pragma unroll
    for (int o = 16; o > 0; o >>= 1) cnt += __shfl_xor_sync(0xffffffffu, cnt, o);

    if (lane == 0) { g_cnt[r] = cnt; g_offset[r] = offset; }
}

// ---------------------------------------------------------------------------
// Kernel 2: exclusive scan over 1040 counts (single block, Hillis-Steele on
// 1024 partials of 2 elements each). Also derives total and L = total/NB.
// ---------------------------------------------------------------------------
__global__ void scan_kernel() {
    __shared__ int sh[1024];
    int t = threadIdx.x;
    int i0 = 2 * t, i1 = 2 * t + 1;
    int a0 = (i0 < NR) ? g_cnt[i0] : 0;
    int a1 = (i1 < NR) ? g_cnt[i1] : 0;
    int s = a0 + a1;
    sh[t] = s;
    __syncthreads();
    #pragma unroll
    for (int off = 1; off < 1024; off <<= 1) {
        int v = (t >= off) ? sh[t - off] : 0;
        __syncthreads();
        sh[t] += v;
        __syncthreads();
    }
    int incl = sh[t];
    int excl = incl - s;
    if (i0 < NR) g_rowstart[i0] = excl;
    if (i1 < NR) g_rowstart[i1] = excl + a0;
    if (t == 1023) {
        g_rowstart[NR] = incl;      // = total masked count
        g_L[0] = incl / NB;
    }
}

// ---------------------------------------------------------------------------
// Kernel 3: gather. One warp per output row (b, t). Binary search rowstart to
// invert the compaction, then interpolate two source rows of x.
// ---------------------------------------------------------------------------
__global__ void gather_kernel(const float* __restrict__ x,
                              const float* __restrict__ scales,
                              float* __restrict__ out) {
    int gid  = (blockIdx.x * blockDim.x + threadIdx.x) >> 5;  // output row id
    int lane = threadIdx.x & 31;
    if (gid >= NB * LSEQ) return;
    int b = gid >> 11;         // / LSEQ
    int t = gid & (LSEQ - 1);

    float4* orow = (float4*)(out + (size_t)gid * ND);
    int L = g_L[0];
    if (t >= L) {
        orow[lane] = make_float4(0.f, 0.f, 0.f, 0.f);
        return;
    }

    int g = b * L + t;         // global compacted slot, g < total
    // upper_bound over rowstart[0..NR]: find r with rowstart[r] <= g < rowstart[r+1]
    int lo = 0, hi = NR;
    while (hi - lo > 1) {
        int mid = (lo + hi) >> 1;
        if (g_rowstart[mid] <= g) lo = mid; else hi = mid;
    }
    int r = lo;
    int w = g - g_rowstart[r];   // prefix property: k-th masked entry is w=k

    float sc = scales[r] + 0.5f;
    float fs = __fdiv_rn((float)w, sc);
    float fl = floorf(fs);
    float lam = fs - fl;
    int i0 = (int)(fl + (float)g_offset[r]);
    i0 = min(max(i0, 0), T_PAD - 1);
    int i1 = min(i0 + 1, T_PAD - 1);
    int bx = r / NS;

    const float4* p0 = (const float4*)(x + ((size_t)bx * T_PAD + i0) * ND);
    const float4* p1 = (const float4*)(x + ((size_t)bx * T_PAD + i1) * ND);
    float4 a = p0[lane];
    float4 c = p1[lane];
    float om = 1.0f - lam;
    float4 y;
    y.x = om * a.x + lam * c.x;
    y.y = om * a.y + lam * c.y;
    y.z = om * a.z + lam * c.z;
    y.w = om * a.w + lam * c.w;
    orow[lane] = y;
}

extern "C" void kernel_launch(void* const* d_in, const int* in_sizes, int n_in,
                              void* d_out, int out_size) {
    const float* x           = (const float*)d_in[0];
    const float* scales      = (const float*)d_in[1];
    const int*   len_seq     = (const int*)d_in[2];
    const int*   len_seg_raw = (const int*)d_in[3];
    float* out = (float*)d_out;

    count_kernel<<<(NR * 32 + 255) / 256, 256>>>(scales, len_seq, len_seg_raw);
    scan_kernel<<<1, 1024>>>();
    gather_kernel<<<(NB * LSEQ * 32) / 256, 256>>>(x, scales, out);
}

// round 2
// speedup vs baseline: 1.0900x; 1.0900x over previous
#include <cuda_runtime.h>

#define NB 16            // batch
#define NS 65            // segments per batch
#define NR 1040          // NB*NS rows
#define NW 256           // candidate positions per row
#define ND 128           // feature dim
#define T_PAD 2176       // padded time length of x
#define LSEQ 2048        // MAX_LEN_SEQ
#define MIN_SEG 32

__device__ int g_offset[NR];
__device__ int g_rowstart[NR + 1];
__device__ int g_L[1];

// ---------------------------------------------------------------------------
// Fused setup: per-batch segment-offset cumsum, per-row masked count via
// binary search (mask is a monotone prefix in w), block-wide exclusive scan.
// Single block, 1024 threads.
// ---------------------------------------------------------------------------
__global__ void __launch_bounds__(1024)
setup_kernel(const float* __restrict__ scales,
             const int* __restrict__ len_seq,
             const int* __restrict__ len_seg_raw) {
    __shared__ int sh_seg[NR];
    __shared__ int sh_off[NR];
    __shared__ int sh_sum[1024];
    int tid = threadIdx.x;

    for (int i = tid; i < NR; i += 1024) sh_seg[i] = len_seg_raw[i] + MIN_SEG;
    __syncthreads();

    // per-batch exclusive cumsum of segment lengths (16 serial scanners)
    if (tid < NB) {
        int acc = 0, base = tid * NS;
        for (int s = 0; s < NS; s++) { sh_off[base + s] = acc; acc += sh_seg[base + s]; }
    }
    __syncthreads();

    // counts for rows 2*tid and 2*tid+1 via binary search over w.
    // mask(w) = floor(rn(w/sc)) < T,  T = min(lseg-1, lseq-1-offset); monotone.
    int a0 = 0, a1 = 0;
    #pragma unroll
    for (int e = 0; e < 2; e++) {
        int r = 2 * tid + e;
        int cnt = 0;
        if (r < NR) {
            int b = r / NS;
            int Tm = min(sh_seg[r] - 1, len_seq[b] - 1 - sh_off[r]);
            float sc = scales[r] + 0.5f;
            float fT = (float)Tm;
            int lo = 0, hi = NW;
            while (lo < hi) {
                int mid = (lo + hi) >> 1;
                float fl = floorf(__fdiv_rn((float)mid, sc));  // exact ref semantics
                if (fl >= fT) hi = mid; else lo = mid + 1;
            }
            cnt = lo;   // first w failing the mask == prefix length
        }
        if (e == 0) a0 = cnt; else a1 = cnt;
    }

    int s = a0 + a1;
    sh_sum[tid] = s;
    __syncthreads();
    #pragma unroll
    for (int off = 1; off < 1024; off <<= 1) {
        int v = (tid >= off) ? sh_sum[tid - off] : 0;
        __syncthreads();
        sh_sum[tid] += v;
        __syncthreads();
    }
    int incl = sh_sum[tid];
    int excl = incl - s;
    int i0 = 2 * tid, i1 = 2 * tid + 1;
    if (i0 < NR) { g_rowstart[i0] = excl;      g_offset[i0] = sh_off[i0]; }
    if (i1 < NR) { g_rowstart[i1] = excl + a0; g_offset[i1] = sh_off[i1]; }
    if (tid == 1023) {
        g_rowstart[NR] = incl;       // total masked count
        g_L[0] = incl / NB;
    }
}

// ---------------------------------------------------------------------------
// Gather: one warp per output row (b, t). Binary search rowstart to invert
// the compaction, then lerp two source rows of x. PDL-synced against setup.
// ---------------------------------------------------------------------------
__global__ void __launch_bounds__(256)
gather_kernel(const float* __restrict__ x,
              const float* __restrict__ scales,
              float* __restrict__ out) {
#if __CUDA_ARCH__ >= 900
    cudaGridDependencySynchronize();   // PDL: wait for setup_kernel results
#endif
    int gid  = (blockIdx.x * blockDim.x + threadIdx.x) >> 5;  // output row id
    int lane = threadIdx.x & 31;
    if (gid >= NB * LSEQ) return;
    int b = gid >> 11;          // / LSEQ
    int t = gid & (LSEQ - 1);

    float4* orow = (float4*)(out + (size_t)gid * ND);
    int L = g_L[0];
    if (t >= L) {
        orow[lane] = make_float4(0.f, 0.f, 0.f, 0.f);
        return;
    }

    int g = b * L + t;          // global compacted slot
    int lo = 0, hi = NR;        // find r: rowstart[r] <= g < rowstart[r+1]
    while (hi - lo > 1) {
        int mid = (lo + hi) >> 1;
        if (g_rowstart[mid] <= g) lo = mid; else hi = mid;
    }
    int r = lo;
    int w = g - g_rowstart[r];  // prefix property: k-th masked entry is w=k

    float sc = scales[r] + 0.5f;
    float fs = __fdiv_rn((float)w, sc);
    float fl = floorf(fs);
    float lam = fs - fl;
    int i0 = (int)(fl + (float)g_offset[r]);
    i0 = min(max(i0, 0), T_PAD - 1);
    int i1 = min(i0 + 1, T_PAD - 1);
    int bx = r / NS;

    const float4* p0 = (const float4*)(x + ((size_t)bx * T_PAD + i0) * ND);
    const float4* p1 = (const float4*)(x + ((size_t)bx * T_PAD + i1) * ND);
    float4 a = p0[lane];
    float4 c = p1[lane];
    float om = 1.0f - lam;
    float4 y;
    y.x = om * a.x + lam * c.x;
    y.y = om * a.y + lam * c.y;
    y.z = om * a.z + lam * c.z;
    y.w = om * a.w + lam * c.w;
    orow[lane] = y;
}

extern "C" void kernel_launch(void* const* d_in, const int* in_sizes, int n_in,
                              void* d_out, int out_size) {
    const float* x           = (const float*)d_in[0];
    const float* scales      = (const float*)d_in[1];
    const int*   len_seq     = (const int*)d_in[2];
    const int*   len_seg_raw = (const int*)d_in[3];
    float* out = (float*)d_out;

    setup_kernel<<<1, 1024>>>(scales, len_seq, len_seg_raw);

    // Gather with programmatic dependent launch: launch overlaps setup tail,
    // data dependency enforced by cudaGridDependencySynchronize() in-kernel.
    cudaLaunchConfig_t cfg = {};
    cfg.gridDim  = dim3((NB * LSEQ * 32) / 256);
    cfg.blockDim = dim3(256);
    cfg.dynamicSmemBytes = 0;
    cfg.stream = 0;
    cudaLaunchAttribute attr[1];
    attr[0].id = cudaLaunchAttributeProgrammaticStreamSerialization;
    attr[0].val.programmaticStreamSerializationAllowed = 1;
    cfg.attrs = attr;
    cfg.numAttrs = 1;
    cudaLaunchKernelEx(&cfg, gather_kernel, x, scales, out);
}